// round 1
// baseline (speedup 1.0000x reference)
#include <cuda_runtime.h>

#define NN 200000
#define NE 1600000
#define NG 2000
#define DD 64
#define NBLK 196   // ceil(NN/1024)

// ---------------- scratch (static device globals; no allocations) ----------
__device__ int   g_deg[NN];
__device__ int   g_off[NN];
__device__ int   g_cur[NN];
__device__ float g_dinv[NN];
__device__ int   g_csr[NE];
__device__ int   g_bsum[256];
__device__ int   g_bsum2[256];
__device__ float g_A[NN * DD];     // node features (post-activation h)
__device__ float g_B[NN * DD];     // transformed+scaled features t = dinv*(h@W)
__device__ float g_gsum[NG * DD];
__device__ float g_cnt[NG];

// ---------------- degree / CSR build ---------------------------------------
__global__ void k_zero() {
    int i = blockIdx.x * blockDim.x + threadIdx.x;
    if (i < NN) g_deg[i] = 0;
    if (i < NG * DD) g_gsum[i] = 0.f;
    if (i < NG) g_cnt[i] = 0.f;
}

__global__ void k_count(const int* __restrict__ ei) {
    int e = blockIdx.x * blockDim.x + threadIdx.x;
    if (e < NE) atomicAdd(&g_deg[ei[NE + e]], 1);
}

__global__ void k_dinv() {
    int i = blockIdx.x * blockDim.x + threadIdx.x;
    if (i < NN) g_dinv[i] = rsqrtf((float)(g_deg[i] + 1));
}

__global__ void k_scanA() {
    __shared__ int s[1024];
    int tid = threadIdx.x;
    int i = blockIdx.x * 1024 + tid;
    int v = (i < NN) ? g_deg[i] : 0;
    s[tid] = v;
    __syncthreads();
    for (int d = 1; d < 1024; d <<= 1) {
        int t = (tid >= d) ? s[tid - d] : 0;
        __syncthreads();
        s[tid] += t;
        __syncthreads();
    }
    if (i < NN) g_off[i] = s[tid] - v;          // exclusive within block
    if (tid == 1023) g_bsum[blockIdx.x] = s[1023];
}

__global__ void k_scanB() {
    __shared__ int s[256];
    int tid = threadIdx.x;
    int v = (tid < NBLK) ? g_bsum[tid] : 0;
    s[tid] = v;
    __syncthreads();
    for (int d = 1; d < 256; d <<= 1) {
        int t = (tid >= d) ? s[tid - d] : 0;
        __syncthreads();
        s[tid] += t;
        __syncthreads();
    }
    g_bsum2[tid] = s[tid] - v;                  // exclusive block offsets
}

__global__ void k_addoff() {
    int i = blockIdx.x * blockDim.x + threadIdx.x;
    if (i < NN) {
        int o = g_off[i] + g_bsum2[i >> 10];
        g_off[i] = o;
        g_cur[i] = o;
    }
}

__global__ void k_fill(const int* __restrict__ ei) {
    int e = blockIdx.x * blockDim.x + threadIdx.x;
    if (e < NE) {
        int d = ei[NE + e];
        int p = atomicAdd(&g_cur[d], 1);
        g_csr[p] = ei[e];
    }
}

// ---------------- transform: t = dinv * (h @ W) -----------------------------
// EMBED=true: h comes from embed_table[x[v]]; else h = g_A (already relu'd).
template <bool EMBED>
__global__ void k_transform(const int* __restrict__ x,
                            const float* __restrict__ emb,
                            const float* __restrict__ W) {
    __shared__ __align__(16) float Ws[64 * 64];
    __shared__ __align__(16) float As[64][68];
    int tid = threadIdx.x;           // 256 threads
    for (int i = tid; i < 4096; i += 256) Ws[i] = W[i];
    int rowbase = blockIdx.x * 64;
#pragma unroll
    for (int q = 0; q < 4; q++) {
        int lin4 = q * 256 + tid;            // float4 index within 64x64 tile
        int r = lin4 >> 4;
        int cc = (lin4 & 15) << 2;
        int v = rowbase + r;
        float4 val;
        if (EMBED) {
            int tok = x[v];
            val = *(const float4*)&emb[tok * 64 + cc];
        } else {
            val = *(const float4*)&g_A[v * 64 + cc];
        }
        *(float4*)&As[r][cc] = val;
    }
    __syncthreads();

    int tx = tid & 15, ty = tid >> 4;
    float acc[4][4] = {};
#pragma unroll
    for (int k = 0; k < 64; k++) {
        float4 bv = *(const float4*)&Ws[k * 64 + tx * 4];
#pragma unroll
        for (int r = 0; r < 4; r++) {
            float a = As[ty * 4 + r][k];
            acc[r][0] = fmaf(a, bv.x, acc[r][0]);
            acc[r][1] = fmaf(a, bv.y, acc[r][1]);
            acc[r][2] = fmaf(a, bv.z, acc[r][2]);
            acc[r][3] = fmaf(a, bv.w, acc[r][3]);
        }
    }
#pragma unroll
    for (int r = 0; r < 4; r++) {
        int v = rowbase + ty * 4 + r;
        float dv = g_dinv[v];
        float4 o = make_float4(acc[r][0] * dv, acc[r][1] * dv,
                               acc[r][2] * dv, acc[r][3] * dv);
        *(float4*)&g_B[v * 64 + tx * 4] = o;
    }
}

// ---------------- gather: A[v] = relu(dinv[v]*(t[v] + sum_in t[src]) + b) ---
__global__ void k_gather(const float* __restrict__ bias) {
    int gw = (blockIdx.x * blockDim.x + threadIdx.x) >> 5;
    if (gw >= NN) return;
    int l = threadIdx.x & 31;
    const float2* tv = (const float2*)g_B;
    float2 acc = __ldg(&tv[gw * 32 + l]);       // self-loop term
    int beg = g_off[gw];
    int dg = g_deg[gw];
    const int* cs = g_csr + beg;
    int i = 0;
    for (; i + 2 <= dg; i += 2) {
        int s0 = __ldg(&cs[i]);
        int s1 = __ldg(&cs[i + 1]);
        float2 v0 = __ldg(&tv[s0 * 32 + l]);
        float2 v1 = __ldg(&tv[s1 * 32 + l]);
        acc.x += v0.x + v1.x;
        acc.y += v0.y + v1.y;
    }
    if (i < dg) {
        int s0 = __ldg(&cs[i]);
        float2 v0 = __ldg(&tv[s0 * 32 + l]);
        acc.x += v0.x;
        acc.y += v0.y;
    }
    float dv = g_dinv[gw];
    float2 bb = __ldg(&((const float2*)bias)[l]);
    float2 o;
    o.x = fmaxf(fmaf(dv, acc.x, bb.x), 0.f);
    o.y = fmaxf(fmaf(dv, acc.y, bb.y), 0.f);
    ((float2*)g_A)[gw * 32 + l] = o;
}

// ---------------- mean pool (batch is sorted: run-length segmented) --------
__global__ void k_pool(const int* __restrict__ batch) {
    int base = blockIdx.x * 128;
    int end = min(base + 128, NN);
    int j = threadIdx.x;                        // 64 threads, one per feature
    int cur = batch[base];
    float acc = 0.f;
    int run = 0;
    for (int v = base; v < end; v++) {
        int gv = batch[v];
        if (gv != cur) {
            atomicAdd(&g_gsum[cur * 64 + j], acc);
            if (j == 0) atomicAdd(&g_cnt[cur], (float)run);
            acc = 0.f;
            run = 0;
            cur = gv;
        }
        acc += g_A[v * 64 + j];
        run++;
    }
    atomicAdd(&g_gsum[cur * 64 + j], acc);
    if (j == 0) atomicAdd(&g_cnt[cur], (float)run);
}

// ---------------- classifier head ------------------------------------------
__global__ void k_final(const float* __restrict__ Wlin,
                        const float* __restrict__ blin,
                        float* __restrict__ out) {
    int g = blockIdx.x * blockDim.x + threadIdx.x;
    if (g >= NG) return;
    float inv = 1.0f / fmaxf(g_cnt[g], 1.0f);
    float a0 = blin[0], a1 = blin[1];
#pragma unroll 8
    for (int j = 0; j < 64; j++) {
        float m = g_gsum[g * 64 + j] * inv;
        a0 = fmaf(m, Wlin[2 * j], a0);
        a1 = fmaf(m, Wlin[2 * j + 1], a1);
    }
    out[2 * g] = a0;
    out[2 * g + 1] = a1;
}

// ---------------- launch ----------------------------------------------------
extern "C" void kernel_launch(void* const* d_in, const int* in_sizes, int n_in,
                              void* d_out, int out_size) {
    const int* x      = (const int*)d_in[0];
    const int* ei     = (const int*)d_in[1];   // [2, NE] row-major
    // d_in[2] = edge_type (unused by GCNConv)
    const int* batch  = (const int*)d_in[3];
    const float* emb  = (const float*)d_in[4];
    const float* W1   = (const float*)d_in[5];
    const float* b1   = (const float*)d_in[6];
    const float* W2   = (const float*)d_in[7];
    const float* b2   = (const float*)d_in[8];
    const float* Wlin = (const float*)d_in[9];
    const float* blin = (const float*)d_in[10];
    float* out = (float*)d_out;

    // degree + CSR-by-dst (counting sort, rebuilt every launch)
    k_zero<<<(NN + 255) / 256, 256>>>();
    k_count<<<(NE + 255) / 256, 256>>>(ei);
    k_dinv<<<(NN + 255) / 256, 256>>>();
    k_scanA<<<NBLK, 1024>>>();
    k_scanB<<<1, 256>>>();
    k_addoff<<<(NN + 255) / 256, 256>>>();
    k_fill<<<(NE + 255) / 256, 256>>>(ei);

    // layer 1: embed fused into GEMM load
    k_transform<true><<<NN / 64, 256>>>(x, emb, W1);
    k_gather<<<NN / 8, 256>>>(b1);

    // layer 2
    k_transform<false><<<NN / 64, 256>>>(nullptr, nullptr, W2);
    k_gather<<<NN / 8, 256>>>(b2);

    // pool + head
    k_pool<<<(NN + 127) / 128, 64>>>(batch);
    k_final<<<(NG + 255) / 256, 256>>>(Wlin, blin, out);
}

// round 2
// speedup vs baseline: 1.3588x; 1.3588x over previous
#include <cuda_runtime.h>

#define NN 200000
#define NE 1600000
#define NG 2000
#define DD 64
#define NVOC 10000
#define NBLK 196   // ceil(NN/1024)

// ---------------- scratch (static device globals; no allocations) ----------
__device__ int   g_deg[NN];
__device__ int   g_off[NN];
__device__ int   g_cur[NN];
__device__ float g_dinv[NN];
__device__ int   g_csr[NE];
__device__ int   g_bsum[256];
__device__ int   g_bsum2[256];
__device__ float g_embW[NVOC * DD];  // emb @ W1
__device__ float g_T1[NN * DD];      // dinv * (h0 @ W1)
__device__ float g_T2[NN * DD];      // dinv * (h1 @ W2)
__device__ float g_gsum[NG * DD];
__device__ float g_cnt[NG];

// ---------------- degree / CSR build ---------------------------------------
__global__ void k_zero() {
    int i = blockIdx.x * blockDim.x + threadIdx.x;
    if (i < NN) g_deg[i] = 0;
    if (i < NG * DD) g_gsum[i] = 0.f;
    if (i < NG) g_cnt[i] = 0.f;
}

__global__ void k_count(const int* __restrict__ ei) {
    int e = blockIdx.x * blockDim.x + threadIdx.x;
    if (e < NE) atomicAdd(&g_deg[ei[NE + e]], 1);
}

__global__ void k_scanA() {
    __shared__ int s[1024];
    int tid = threadIdx.x;
    int i = blockIdx.x * 1024 + tid;
    int v = (i < NN) ? g_deg[i] : 0;
    s[tid] = v;
    __syncthreads();
    for (int d = 1; d < 1024; d <<= 1) {
        int t = (tid >= d) ? s[tid - d] : 0;
        __syncthreads();
        s[tid] += t;
        __syncthreads();
    }
    if (i < NN) g_off[i] = s[tid] - v;          // exclusive within block
    if (tid == 1023) g_bsum[blockIdx.x] = s[1023];
}

__global__ void k_scanB() {
    __shared__ int s[256];
    int tid = threadIdx.x;
    int v = (tid < NBLK) ? g_bsum[tid] : 0;
    s[tid] = v;
    __syncthreads();
    for (int d = 1; d < 256; d <<= 1) {
        int t = (tid >= d) ? s[tid - d] : 0;
        __syncthreads();
        s[tid] += t;
        __syncthreads();
    }
    g_bsum2[tid] = s[tid] - v;                  // exclusive block offsets
}

__global__ void k_addoff() {
    int i = blockIdx.x * blockDim.x + threadIdx.x;
    if (i < NN) {
        int o = g_off[i] + g_bsum2[i >> 10];
        g_off[i] = o;
        g_cur[i] = o;
        g_dinv[i] = rsqrtf((float)(g_deg[i] + 1));
    }
}

__global__ void k_fill(const int* __restrict__ ei) {
    int e = blockIdx.x * blockDim.x + threadIdx.x;
    if (e < NE) {
        int d = ei[NE + e];
        int p = atomicAdd(&g_cur[d], 1);
        g_csr[p] = ei[e];
    }
}

// ---------------- embW = emb @ W1 (vocab-sized GEMM, 10000x64 @ 64x64) ------
__global__ void k_embW(const float* __restrict__ emb,
                       const float* __restrict__ W) {
    __shared__ __align__(16) float Ws[64 * 64];
    __shared__ __align__(16) float As[64][68];
    int tid = threadIdx.x;           // 256 threads
    for (int i = tid; i < 4096; i += 256) Ws[i] = W[i];
    int rowbase = blockIdx.x * 64;
#pragma unroll
    for (int q = 0; q < 4; q++) {
        int lin4 = q * 256 + tid;
        int r = lin4 >> 4;
        int cc = (lin4 & 15) << 2;
        int v = rowbase + r;
        float4 val = make_float4(0.f, 0.f, 0.f, 0.f);
        if (v < NVOC) val = *(const float4*)&emb[v * 64 + cc];
        *(float4*)&As[r][cc] = val;
    }
    __syncthreads();

    int tx = tid & 15, ty = tid >> 4;
    float acc[4][4] = {};
#pragma unroll
    for (int k = 0; k < 64; k++) {
        float4 bv = *(const float4*)&Ws[k * 64 + tx * 4];
#pragma unroll
        for (int r = 0; r < 4; r++) {
            float a = As[ty * 4 + r][k];
            acc[r][0] = fmaf(a, bv.x, acc[r][0]);
            acc[r][1] = fmaf(a, bv.y, acc[r][1]);
            acc[r][2] = fmaf(a, bv.z, acc[r][2]);
            acc[r][3] = fmaf(a, bv.w, acc[r][3]);
        }
    }
#pragma unroll
    for (int r = 0; r < 4; r++) {
        int v = rowbase + ty * 4 + r;
        if (v < NVOC) {
            float4 o = make_float4(acc[r][0], acc[r][1], acc[r][2], acc[r][3]);
            *(float4*)&g_embW[v * 64 + tx * 4] = o;
        }
    }
}

// ---------------- seed: T1[v] = dinv[v] * embW[x[v]] ------------------------
__global__ void k_seed(const int* __restrict__ x) {
    int t = blockIdx.x * blockDim.x + threadIdx.x;   // one float4 per thread
    if (t >= NN * 16) return;
    int v = t >> 4;
    int c = (t & 15) << 2;
    int tok = __ldg(&x[v]);
    float dv = g_dinv[v];
    float4 e = *(const float4*)&g_embW[tok * 64 + c];
    float4 o = make_float4(e.x * dv, e.y * dv, e.z * dv, e.w * dv);
    *(float4*)&g_T1[v * 64 + c] = o;
}

// ---------------- gather helper ---------------------------------------------
__device__ __forceinline__ float2 gather_node(const float2* __restrict__ tv,
                                              int v, int l) {
    float2 acc = __ldg(&tv[v * 32 + l]);        // self-loop term
    int beg = g_off[v];
    int dg = g_deg[v];
    const int* cs = g_csr + beg;
    int i = 0;
    for (; i + 4 <= dg; i += 4) {
        int s0 = __ldg(&cs[i]);
        int s1 = __ldg(&cs[i + 1]);
        int s2 = __ldg(&cs[i + 2]);
        int s3 = __ldg(&cs[i + 3]);
        float2 v0 = __ldg(&tv[s0 * 32 + l]);
        float2 v1 = __ldg(&tv[s1 * 32 + l]);
        float2 v2 = __ldg(&tv[s2 * 32 + l]);
        float2 v3 = __ldg(&tv[s3 * 32 + l]);
        acc.x += (v0.x + v1.x) + (v2.x + v3.x);
        acc.y += (v0.y + v1.y) + (v2.y + v3.y);
    }
    for (; i < dg; i++) {
        int s0 = __ldg(&cs[i]);
        float2 v0 = __ldg(&tv[s0 * 32 + l]);
        acc.x += v0.x;
        acc.y += v0.y;
    }
    return acc;
}

// ---------------- layer1 gather + layer2 transform fused --------------------
// h1 = relu(dinv*(gather T1) + b1)  (to smem), then T2 = dinv*(h1 @ W2)
__global__ void k_gather_gemm(const float* __restrict__ b1,
                              const float* __restrict__ W2) {
    __shared__ __align__(16) float Ws[64 * 64];
    __shared__ __align__(16) float As[64][68];
    int tid = threadIdx.x;           // 256 threads
    int w = tid >> 5, l = tid & 31;
    for (int i = tid; i < 4096; i += 256) Ws[i] = W2[i];
    int base = blockIdx.x * 64;
    float2 bb = __ldg(&((const float2*)b1)[l]);
    const float2* tv = (const float2*)g_T1;
#pragma unroll 1
    for (int n = 0; n < 8; n++) {
        int v = base + w * 8 + n;
        float2 acc = gather_node(tv, v, l);
        float dv = g_dinv[v];
        float2 o;
        o.x = fmaxf(fmaf(dv, acc.x, bb.x), 0.f);
        o.y = fmaxf(fmaf(dv, acc.y, bb.y), 0.f);
        *(float2*)&As[w * 8 + n][2 * l] = o;
    }
    __syncthreads();

    int tx = tid & 15, ty = tid >> 4;
    float acc[4][4] = {};
#pragma unroll
    for (int k = 0; k < 64; k++) {
        float4 bv = *(const float4*)&Ws[k * 64 + tx * 4];
#pragma unroll
        for (int r = 0; r < 4; r++) {
            float a = As[ty * 4 + r][k];
            acc[r][0] = fmaf(a, bv.x, acc[r][0]);
            acc[r][1] = fmaf(a, bv.y, acc[r][1]);
            acc[r][2] = fmaf(a, bv.z, acc[r][2]);
            acc[r][3] = fmaf(a, bv.w, acc[r][3]);
        }
    }
#pragma unroll
    for (int r = 0; r < 4; r++) {
        int v = base + ty * 4 + r;
        float dv = g_dinv[v];
        float4 o = make_float4(acc[r][0] * dv, acc[r][1] * dv,
                               acc[r][2] * dv, acc[r][3] * dv);
        *(float4*)&g_T2[v * 64 + tx * 4] = o;
    }
}

// ---------------- layer2 gather + mean-pool fused ---------------------------
// h2 = relu(dinv*(gather T2) + b2) (to smem), then run-length pool into gsum.
__global__ void k_gather_pool(const float* __restrict__ b2,
                              const int* __restrict__ batch) {
    __shared__ __align__(16) float As[64][68];
    __shared__ int sb[64];
    int tid = threadIdx.x;           // 256 threads
    int w = tid >> 5, l = tid & 31;
    int base = blockIdx.x * 64;
    if (tid < 64) sb[tid] = batch[base + tid];
    float2 bb = __ldg(&((const float2*)b2)[l]);
    const float2* tv = (const float2*)g_T2;
#pragma unroll 1
    for (int n = 0; n < 8; n++) {
        int v = base + w * 8 + n;
        float2 acc = gather_node(tv, v, l);
        float dv = g_dinv[v];
        float2 o;
        o.x = fmaxf(fmaf(dv, acc.x, bb.x), 0.f);
        o.y = fmaxf(fmaf(dv, acc.y, bb.y), 0.f);
        *(float2*)&As[w * 8 + n][2 * l] = o;
    }
    __syncthreads();

    // 64 threads: run-length pool over the 64 smem rows (batch is sorted)
    if (tid < 64) {
        int j = tid;
        int cur = sb[0];
        float acc = 0.f;
        int run = 0;
#pragma unroll 1
        for (int n = 0; n < 64; n++) {
            int gv = sb[n];
            if (gv != cur) {
                atomicAdd(&g_gsum[cur * 64 + j], acc);
                if (j == 0) atomicAdd(&g_cnt[cur], (float)run);
                acc = 0.f;
                run = 0;
                cur = gv;
            }
            acc += As[n][j];
            run++;
        }
        atomicAdd(&g_gsum[cur * 64 + j], acc);
        if (j == 0) atomicAdd(&g_cnt[cur], (float)run);
    }
}

// ---------------- classifier head ------------------------------------------
__global__ void k_final(const float* __restrict__ Wlin,
                        const float* __restrict__ blin,
                        float* __restrict__ out) {
    int g = blockIdx.x * blockDim.x + threadIdx.x;
    if (g >= NG) return;
    float inv = 1.0f / fmaxf(g_cnt[g], 1.0f);
    float a0 = blin[0], a1 = blin[1];
#pragma unroll 8
    for (int j = 0; j < 64; j++) {
        float m = g_gsum[g * 64 + j] * inv;
        a0 = fmaf(m, Wlin[2 * j], a0);
        a1 = fmaf(m, Wlin[2 * j + 1], a1);
    }
    out[2 * g] = a0;
    out[2 * g + 1] = a1;
}

// ---------------- launch ----------------------------------------------------
extern "C" void kernel_launch(void* const* d_in, const int* in_sizes, int n_in,
                              void* d_out, int out_size) {
    const int* x      = (const int*)d_in[0];
    const int* ei     = (const int*)d_in[1];   // [2, NE] row-major
    // d_in[2] = edge_type (unused by GCNConv)
    const int* batch  = (const int*)d_in[3];
    const float* emb  = (const float*)d_in[4];
    const float* W1   = (const float*)d_in[5];
    const float* b1   = (const float*)d_in[6];
    const float* W2   = (const float*)d_in[7];
    const float* b2   = (const float*)d_in[8];
    const float* Wlin = (const float*)d_in[9];
    const float* blin = (const float*)d_in[10];
    float* out = (float*)d_out;

    // degree + CSR-by-dst (counting sort, rebuilt every launch)
    k_zero<<<(NN + 255) / 256, 256>>>();
    k_count<<<(NE + 255) / 256, 256>>>(ei);
    k_scanA<<<NBLK, 1024>>>();
    k_scanB<<<1, 256>>>();
    k_addoff<<<(NN + 255) / 256, 256>>>();
    k_fill<<<(NE + 255) / 256, 256>>>(ei);

    // embW = emb @ W1, then T1 = dinv * embW[x]
    k_embW<<<(NVOC + 63) / 64, 256>>>(emb, W1);
    k_seed<<<(NN * 16 + 255) / 256, 256>>>(x);

    // layer 1 gather + layer 2 transform (fused)
    k_gather_gemm<<<NN / 64, 256>>>(b1, W2);

    // layer 2 gather + mean pool (fused)
    k_gather_pool<<<NN / 64, 256>>>(b2, batch);

    // head
    k_final<<<(NG + 255) / 256, 256>>>(Wlin, blin, out);
}

// round 3
// speedup vs baseline: 1.5566x; 1.1456x over previous
#include <cuda_runtime.h>
#include <cuda_fp16.h>

#define NN 200000
#define NE 1600000
#define NG 2000
#define DD 64
#define NVOC 10000
#define NBLK 196   // ceil(NN/1024)

// ---------------- scratch (static device globals; no allocations) ----------
__device__ int     g_deg[NN];
__device__ int     g_off[NN];
__device__ int     g_cur[NN];
__device__ float   g_dinv[NN];
__device__ int     g_csr[NE];
__device__ int     g_alloc;
__device__ float   g_embW[NVOC * DD];   // emb @ W1 (fp32, 2.5MB, L2-hot)
__device__ __half2 g_T1h[NN * 32];      // dinv * (h0 @ W1), fp16 (25.6MB)
__device__ __half2 g_T2h[NN * 32];      // dinv * (h1 @ W2), fp16
__device__ float   g_gsum[NG * DD];
__device__ float   g_cnt[NG];

// ---------------- degree count (also resets the allocator) -----------------
__global__ void k_count(const int* __restrict__ ei) {
    int e = blockIdx.x * blockDim.x + threadIdx.x;
    if (e == 0) g_alloc = 0;
    if (e < NE) atomicAdd(&g_deg[__ldg(&ei[NE + e])], 1);
}

// ---------------- one-pass scan: disjoint CSR segments (order-free) --------
__global__ void k_scan() {
    int tid = threadIdx.x;
    int lane = tid & 31, wid = tid >> 5;
    int i = blockIdx.x * 1024 + tid;
    int v = (i < NN) ? g_deg[i] : 0;

    int xv = v;
#pragma unroll
    for (int d = 1; d < 32; d <<= 1) {
        int t = __shfl_up_sync(0xffffffffu, xv, d);
        if (lane >= d) xv += t;
    }
    __shared__ int wsum[32];
    if (lane == 31) wsum[wid] = xv;
    __syncthreads();
    if (tid < 32) {
        int y = wsum[tid];
#pragma unroll
        for (int d = 1; d < 32; d <<= 1) {
            int t = __shfl_up_sync(0xffffffffu, y, d);
            if (tid >= d) y += t;
        }
        wsum[tid] = y;
    }
    __syncthreads();
    int incl = xv + (wid > 0 ? wsum[wid - 1] : 0);

    __shared__ int sbase;
    if (tid == 1023) sbase = atomicAdd(&g_alloc, incl);  // incl == block total
    __syncthreads();

    if (i < NN) {
        int excl = sbase + incl - v;
        g_off[i] = excl;
        g_cur[i] = excl;
        g_dinv[i] = rsqrtf((float)(v + 1));
    }
}

__global__ void k_fill(const int* __restrict__ ei) {
    int e = blockIdx.x * blockDim.x + threadIdx.x;
    if (e < NE) {
        int d = __ldg(&ei[NE + e]);
        int p = atomicAdd(&g_cur[d], 1);
        g_csr[p] = __ldg(&ei[e]);
    }
}

// ---------------- embW = emb @ W1 (10000x64 @ 64x64) ------------------------
__global__ void k_embW(const float* __restrict__ emb,
                       const float* __restrict__ W) {
    __shared__ __align__(16) float Ws[64 * 64];
    __shared__ __align__(16) float As[64][68];
    int tid = threadIdx.x;           // 256 threads
    for (int i = tid; i < 4096; i += 256) Ws[i] = W[i];
    int rowbase = blockIdx.x * 64;
#pragma unroll
    for (int q = 0; q < 4; q++) {
        int lin4 = q * 256 + tid;
        int r = lin4 >> 4;
        int cc = (lin4 & 15) << 2;
        int v = rowbase + r;
        float4 val = make_float4(0.f, 0.f, 0.f, 0.f);
        if (v < NVOC) val = *(const float4*)&emb[v * 64 + cc];
        *(float4*)&As[r][cc] = val;
    }
    __syncthreads();

    int tx = tid & 15, ty = tid >> 4;
    float acc[4][4] = {};
#pragma unroll
    for (int k = 0; k < 64; k++) {
        float4 bv = *(const float4*)&Ws[k * 64 + tx * 4];
#pragma unroll
        for (int r = 0; r < 4; r++) {
            float a = As[ty * 4 + r][k];
            acc[r][0] = fmaf(a, bv.x, acc[r][0]);
            acc[r][1] = fmaf(a, bv.y, acc[r][1]);
            acc[r][2] = fmaf(a, bv.z, acc[r][2]);
            acc[r][3] = fmaf(a, bv.w, acc[r][3]);
        }
    }
#pragma unroll
    for (int r = 0; r < 4; r++) {
        int v = rowbase + ty * 4 + r;
        if (v < NVOC)
            *(float4*)&g_embW[v * 64 + tx * 4] =
                make_float4(acc[r][0], acc[r][1], acc[r][2], acc[r][3]);
    }
}

// ---------------- seed: T1[v] = fp16(dinv[v] * embW[x[v]]); zero pool bufs --
__global__ void k_seed(const int* __restrict__ x) {
    int t = blockIdx.x * blockDim.x + threadIdx.x;
    if (t < NG * DD) g_gsum[t] = 0.f;
    if (t < NG) g_cnt[t] = 0.f;
    if (t >= NN * 32) return;
    int v = t >> 5, c = t & 31;
    int tok = __ldg(&x[v]);
    float dv = g_dinv[v];
    float2 e = *(const float2*)&g_embW[tok * 64 + 2 * c];
    g_T1h[t] = __floats2half2_rn(e.x * dv, e.y * dv);
}

// ---------------- gather accumulate (fp32 acc, fp16 rows) -------------------
__device__ __forceinline__ float2 gather_accum(const __half2* __restrict__ tv,
                                               int off, int dg, int l,
                                               float2 acc) {
    const int* cs = g_csr + off;
    int i = 0;
    for (; i + 8 <= dg; i += 8) {
        int s[8];
#pragma unroll
        for (int j = 0; j < 8; j++) s[j] = __ldg(&cs[i + j]);
        float2 v[8];
#pragma unroll
        for (int j = 0; j < 8; j++) v[j] = __half22float2(__ldg(&tv[s[j] * 32 + l]));
        acc.x += ((v[0].x + v[1].x) + (v[2].x + v[3].x)) +
                 ((v[4].x + v[5].x) + (v[6].x + v[7].x));
        acc.y += ((v[0].y + v[1].y) + (v[2].y + v[3].y)) +
                 ((v[4].y + v[5].y) + (v[6].y + v[7].y));
    }
    for (; i + 2 <= dg; i += 2) {
        int s0 = __ldg(&cs[i]), s1 = __ldg(&cs[i + 1]);
        float2 v0 = __half22float2(__ldg(&tv[s0 * 32 + l]));
        float2 v1 = __half22float2(__ldg(&tv[s1 * 32 + l]));
        acc.x += v0.x + v1.x;
        acc.y += v0.y + v1.y;
    }
    if (i < dg) {
        float2 v0 = __half22float2(__ldg(&tv[__ldg(&cs[i]) * 32 + l]));
        acc.x += v0.x;
        acc.y += v0.y;
    }
    return acc;
}

// ---------------- layer1 gather + layer2 transform fused --------------------
__global__ void k_gather_gemm(const float* __restrict__ b1,
                              const float* __restrict__ W2) {
    __shared__ __align__(16) float Ws[64 * 64];
    __shared__ __align__(16) float As[64][68];
    int tid = threadIdx.x;           // 256 threads
    int w = tid >> 5, l = tid & 31;
    for (int i = tid; i < 4096; i += 256) Ws[i] = W2[i];
    int base = blockIdx.x * 64;
    float2 bb = __ldg(&((const float2*)b1)[l]);

    int offp = 0, degp = 0;
    if (l < 8) {
        int nv = base + (w << 3) + l;
        offp = g_off[nv];
        degp = g_deg[nv];
    }
#pragma unroll 1
    for (int n = 0; n < 8; n++) {
        int v = base + (w << 3) + n;
        int off = __shfl_sync(0xffffffffu, offp, n);
        int dg  = __shfl_sync(0xffffffffu, degp, n);
        float2 acc = __half22float2(__ldg(&g_T1h[v * 32 + l]));  // self loop
        acc = gather_accum(g_T1h, off, dg, l, acc);
        float dv = g_dinv[v];
        float2 o;
        o.x = fmaxf(fmaf(dv, acc.x, bb.x), 0.f);
        o.y = fmaxf(fmaf(dv, acc.y, bb.y), 0.f);
        *(float2*)&As[(w << 3) + n][2 * l] = o;
    }
    __syncthreads();

    int tx = tid & 15, ty = tid >> 4;
    float acc[4][4] = {};
#pragma unroll
    for (int k = 0; k < 64; k++) {
        float4 bv = *(const float4*)&Ws[k * 64 + tx * 4];
#pragma unroll
        for (int r = 0; r < 4; r++) {
            float a = As[ty * 4 + r][k];
            acc[r][0] = fmaf(a, bv.x, acc[r][0]);
            acc[r][1] = fmaf(a, bv.y, acc[r][1]);
            acc[r][2] = fmaf(a, bv.z, acc[r][2]);
            acc[r][3] = fmaf(a, bv.w, acc[r][3]);
        }
    }
#pragma unroll
    for (int r = 0; r < 4; r++) {
        int v = base + ty * 4 + r;
        float dv = g_dinv[v];
        g_T2h[v * 32 + tx * 2]     = __floats2half2_rn(acc[r][0] * dv, acc[r][1] * dv);
        g_T2h[v * 32 + tx * 2 + 1] = __floats2half2_rn(acc[r][2] * dv, acc[r][3] * dv);
    }
}

// ---------------- layer2 gather + mean-pool fused ---------------------------
__global__ void k_gather_pool(const float* __restrict__ b2,
                              const int* __restrict__ batch) {
    __shared__ __align__(16) float As[64][68];
    __shared__ int sb[64];
    int tid = threadIdx.x;           // 256 threads
    int w = tid >> 5, l = tid & 31;
    int base = blockIdx.x * 64;
    if (tid < 64) sb[tid] = __ldg(&batch[base + tid]);
    float2 bb = __ldg(&((const float2*)b2)[l]);

    int offp = 0, degp = 0;
    if (l < 8) {
        int nv = base + (w << 3) + l;
        offp = g_off[nv];
        degp = g_deg[nv];
    }
#pragma unroll 1
    for (int n = 0; n < 8; n++) {
        int v = base + (w << 3) + n;
        int off = __shfl_sync(0xffffffffu, offp, n);
        int dg  = __shfl_sync(0xffffffffu, degp, n);
        float2 acc = __half22float2(__ldg(&g_T2h[v * 32 + l]));  // self loop
        acc = gather_accum(g_T2h, off, dg, l, acc);
        float dv = g_dinv[v];
        float2 o;
        o.x = fmaxf(fmaf(dv, acc.x, bb.x), 0.f);
        o.y = fmaxf(fmaf(dv, acc.y, bb.y), 0.f);
        *(float2*)&As[(w << 3) + n][2 * l] = o;
    }
    __syncthreads();

    // 64 threads: run-length pool over the 64 smem rows (batch is sorted)
    if (tid < 64) {
        int j = tid;
        int cur = sb[0];
        float acc = 0.f;
        int run = 0;
#pragma unroll 1
        for (int n = 0; n < 64; n++) {
            int gv = sb[n];
            if (gv != cur) {
                atomicAdd(&g_gsum[cur * 64 + j], acc);
                if (j == 0) atomicAdd(&g_cnt[cur], (float)run);
                acc = 0.f;
                run = 0;
                cur = gv;
            }
            acc += As[n][j];
            run++;
        }
        atomicAdd(&g_gsum[cur * 64 + j], acc);
        if (j == 0) atomicAdd(&g_cnt[cur], (float)run);
    }
}

// ---------------- classifier head ------------------------------------------
__global__ void k_final(const float* __restrict__ Wlin,
                        const float* __restrict__ blin,
                        float* __restrict__ out) {
    int g = blockIdx.x * blockDim.x + threadIdx.x;
    if (g >= NG) return;
    float inv = 1.0f / fmaxf(g_cnt[g], 1.0f);
    float a0 = blin[0], a1 = blin[1];
#pragma unroll 8
    for (int j = 0; j < 64; j++) {
        float m = g_gsum[g * 64 + j] * inv;
        a0 = fmaf(m, Wlin[2 * j], a0);
        a1 = fmaf(m, Wlin[2 * j + 1], a1);
    }
    out[2 * g] = a0;
    out[2 * g + 1] = a1;
}

// ---------------- launch ----------------------------------------------------
extern "C" void kernel_launch(void* const* d_in, const int* in_sizes, int n_in,
                              void* d_out, int out_size) {
    const int* x      = (const int*)d_in[0];
    const int* ei     = (const int*)d_in[1];   // [2, NE] row-major
    // d_in[2] = edge_type (unused by GCNConv)
    const int* batch  = (const int*)d_in[3];
    const float* emb  = (const float*)d_in[4];
    const float* W1   = (const float*)d_in[5];
    const float* b1   = (const float*)d_in[6];
    const float* W2   = (const float*)d_in[7];
    const float* b2   = (const float*)d_in[8];
    const float* Wlin = (const float*)d_in[9];
    const float* blin = (const float*)d_in[10];
    float* out = (float*)d_out;

    void* degp = nullptr;
    cudaGetSymbolAddress(&degp, g_deg);
    cudaMemsetAsync(degp, 0, NN * sizeof(int));

    k_count<<<(NE + 255) / 256, 256>>>(ei);
    k_scan<<<NBLK, 1024>>>();
    k_fill<<<(NE + 255) / 256, 256>>>(ei);

    k_embW<<<(NVOC + 63) / 64, 256>>>(emb, W1);
    k_seed<<<(NN * 32 + 255) / 256, 256>>>(x);

    k_gather_gemm<<<NN / 64, 256>>>(b1, W2);
    k_gather_pool<<<NN / 64, 256>>>(b2, batch);

    k_final<<<(NG + 255) / 256, 256>>>(Wlin, blin, out);
}

// round 4
// speedup vs baseline: 1.6059x; 1.0317x over previous
#include <cuda_runtime.h>
#include <cuda_fp16.h>

#define NN 200000
#define NE 1600000
#define NG 2000
#define DD 64
#define NVOC 10000
#define NBLK 196   // ceil(NN/1024)

// ---------------- scratch (static device globals; no allocations) ----------
__device__ int     g_deg[NN];
__device__ int     g_off[NN];
__device__ int     g_cur[NN];
__device__ float   g_dinv[NN];
__device__ int     g_csr[NE];
__device__ int     g_alloc;
__device__ __half2 g_embWh[NVOC * 32];  // fp16(emb @ W1), 1.25MB, L2-hot
__device__ __half2 g_T2h[NN * 32];      // fp16(dinv * (h1 @ W2)), 25.6MB
__device__ float   g_gsum[NG * DD];
__device__ float   g_cnt[NG];

// ---------------- degree count (4 edges/thread) + zero pool bufs ------------
__global__ void k_count(const int* __restrict__ ei) {
    int t = blockIdx.x * blockDim.x + threadIdx.x;
    if (t == 0) g_alloc = 0;
    if (t < NG * DD) g_gsum[t] = 0.f;
    if (t < NG) g_cnt[t] = 0.f;
    int e = t * 4;
    if (e < NE) {
        int4 d4 = *(const int4*)&ei[NE + e];
        atomicAdd(&g_deg[d4.x], 1);
        atomicAdd(&g_deg[d4.y], 1);
        atomicAdd(&g_deg[d4.z], 1);
        atomicAdd(&g_deg[d4.w], 1);
    }
}

// ---------------- one-pass scan: disjoint CSR segments (order-free) --------
__global__ void k_scan() {
    int tid = threadIdx.x;
    int lane = tid & 31, wid = tid >> 5;
    int i = blockIdx.x * 1024 + tid;
    int v = (i < NN) ? g_deg[i] : 0;

    int xv = v;
#pragma unroll
    for (int d = 1; d < 32; d <<= 1) {
        int t = __shfl_up_sync(0xffffffffu, xv, d);
        if (lane >= d) xv += t;
    }
    __shared__ int wsum[32];
    if (lane == 31) wsum[wid] = xv;
    __syncthreads();
    if (tid < 32) {
        int y = wsum[tid];
#pragma unroll
        for (int d = 1; d < 32; d <<= 1) {
            int t = __shfl_up_sync(0xffffffffu, y, d);
            if (tid >= d) y += t;
        }
        wsum[tid] = y;
    }
    __syncthreads();
    int incl = xv + (wid > 0 ? wsum[wid - 1] : 0);

    __shared__ int sbase;
    if (tid == 1023) sbase = atomicAdd(&g_alloc, incl);  // incl == block total
    __syncthreads();

    if (i < NN) {
        int excl = sbase + incl - v;
        g_off[i] = excl;
        g_cur[i] = excl;
        g_dinv[i] = rsqrtf((float)(v + 1));
    }
}

__global__ void k_fill(const int* __restrict__ ei) {
    int e = (blockIdx.x * blockDim.x + threadIdx.x) * 4;
    if (e < NE) {
        int4 d4 = *(const int4*)&ei[NE + e];
        int4 s4 = *(const int4*)&ei[e];
        int p0 = atomicAdd(&g_cur[d4.x], 1);
        int p1 = atomicAdd(&g_cur[d4.y], 1);
        int p2 = atomicAdd(&g_cur[d4.z], 1);
        int p3 = atomicAdd(&g_cur[d4.w], 1);
        g_csr[p0] = s4.x;
        g_csr[p1] = s4.y;
        g_csr[p2] = s4.z;
        g_csr[p3] = s4.w;
    }
}

// ---------------- embWh = fp16(emb @ W1), 512 threads, 2x4 tile -------------
__global__ void k_embW(const float* __restrict__ emb,
                       const float* __restrict__ W) {
    __shared__ __align__(16) float Ws[64 * 64];
    __shared__ __align__(16) float As[64][68];
    int tid = threadIdx.x;           // 512 threads
    for (int i = tid; i < 4096; i += 512) Ws[i] = W[i];
    int rowbase = blockIdx.x * 64;
#pragma unroll
    for (int q = 0; q < 2; q++) {
        int lin4 = q * 512 + tid;
        int r = lin4 >> 4;
        int cc = (lin4 & 15) << 2;
        int v = rowbase + r;
        float4 val = make_float4(0.f, 0.f, 0.f, 0.f);
        if (v < NVOC) val = *(const float4*)&emb[v * 64 + cc];
        *(float4*)&As[r][cc] = val;
    }
    __syncthreads();

    int tx = tid & 15, ty = tid >> 4;      // ty: 0..31
    float acc[2][4] = {};
#pragma unroll
    for (int k = 0; k < 64; k++) {
        float4 bv = *(const float4*)&Ws[k * 64 + tx * 4];
#pragma unroll
        for (int r = 0; r < 2; r++) {
            float a = As[ty * 2 + r][k];
            acc[r][0] = fmaf(a, bv.x, acc[r][0]);
            acc[r][1] = fmaf(a, bv.y, acc[r][1]);
            acc[r][2] = fmaf(a, bv.z, acc[r][2]);
            acc[r][3] = fmaf(a, bv.w, acc[r][3]);
        }
    }
#pragma unroll
    for (int r = 0; r < 2; r++) {
        int v = rowbase + ty * 2 + r;
        if (v < NVOC) {
            g_embWh[v * 32 + tx * 2]     = __floats2half2_rn(acc[r][0], acc[r][1]);
            g_embWh[v * 32 + tx * 2 + 1] = __floats2half2_rn(acc[r][2], acc[r][3]);
        }
    }
}

// ---------------- gather from embW table: acc += dinv[s]*embWh[x[s]] --------
__device__ __forceinline__ float2 gather_emb(const int* __restrict__ x,
                                             int off, int dg, int l,
                                             float2 acc) {
    const int* cs = g_csr + off;
    int i = 0;
    for (; i + 8 <= dg; i += 8) {
        int s[8];
#pragma unroll
        for (int j = 0; j < 8; j++) s[j] = __ldg(&cs[i + j]);
        int xs[8];
#pragma unroll
        for (int j = 0; j < 8; j++) xs[j] = __ldg(&x[s[j]]);
        float ds[8];
#pragma unroll
        for (int j = 0; j < 8; j++) ds[j] = __ldg(&g_dinv[s[j]]);
#pragma unroll
        for (int j = 0; j < 8; j++) {
            float2 v = __half22float2(__ldg(&g_embWh[xs[j] * 32 + l]));
            acc.x = fmaf(ds[j], v.x, acc.x);
            acc.y = fmaf(ds[j], v.y, acc.y);
        }
    }
    for (; i < dg; i++) {
        int s0 = __ldg(&cs[i]);
        int xs = __ldg(&x[s0]);
        float ds = __ldg(&g_dinv[s0]);
        float2 v = __half22float2(__ldg(&g_embWh[xs * 32 + l]));
        acc.x = fmaf(ds, v.x, acc.x);
        acc.y = fmaf(ds, v.y, acc.y);
    }
    return acc;
}

// ---------------- gather from T2 buffer --------------------------------------
__device__ __forceinline__ float2 gather_T2(int off, int dg, int l, float2 acc) {
    const int* cs = g_csr + off;
    int i = 0;
    for (; i + 8 <= dg; i += 8) {
        int s[8];
#pragma unroll
        for (int j = 0; j < 8; j++) s[j] = __ldg(&cs[i + j]);
        float2 v[8];
#pragma unroll
        for (int j = 0; j < 8; j++) v[j] = __half22float2(__ldg(&g_T2h[s[j] * 32 + l]));
        acc.x += ((v[0].x + v[1].x) + (v[2].x + v[3].x)) +
                 ((v[4].x + v[5].x) + (v[6].x + v[7].x));
        acc.y += ((v[0].y + v[1].y) + (v[2].y + v[3].y)) +
                 ((v[4].y + v[5].y) + (v[6].y + v[7].y));
    }
    for (; i + 2 <= dg; i += 2) {
        int s0 = __ldg(&cs[i]), s1 = __ldg(&cs[i + 1]);
        float2 v0 = __half22float2(__ldg(&g_T2h[s0 * 32 + l]));
        float2 v1 = __half22float2(__ldg(&g_T2h[s1 * 32 + l]));
        acc.x += v0.x + v1.x;
        acc.y += v0.y + v1.y;
    }
    if (i < dg) {
        float2 v0 = __half22float2(__ldg(&g_T2h[__ldg(&cs[i]) * 32 + l]));
        acc.x += v0.x;
        acc.y += v0.y;
    }
    return acc;
}

// ---------------- layer1 gather (from embW table) + layer2 transform --------
__global__ void k_gather_gemm(const int* __restrict__ x,
                              const float* __restrict__ b1,
                              const float* __restrict__ W2) {
    __shared__ __align__(16) float Ws[64 * 64];
    __shared__ __align__(16) float As[64][68];
    int tid = threadIdx.x;           // 256 threads
    int w = tid >> 5, l = tid & 31;
    for (int i = tid; i < 4096; i += 256) Ws[i] = W2[i];
    int base = blockIdx.x * 64;
    float2 bb = __ldg(&((const float2*)b1)[l]);

    int offp = 0, degp = 0, tokp = 0;
    float dvp = 0.f;
    if (l < 8) {
        int nv = base + (w << 3) + l;
        offp = g_off[nv];
        degp = g_deg[nv];
        tokp = __ldg(&x[nv]);
        dvp  = g_dinv[nv];
    }
#pragma unroll 1
    for (int n = 0; n < 8; n++) {
        int off = __shfl_sync(0xffffffffu, offp, n);
        int dg  = __shfl_sync(0xffffffffu, degp, n);
        int tok = __shfl_sync(0xffffffffu, tokp, n);
        float dv = __shfl_sync(0xffffffffu, dvp, n);
        // self-loop term: dinv[v]*embWh[x[v]]
        float2 e = __half22float2(__ldg(&g_embWh[tok * 32 + l]));
        float2 acc = make_float2(dv * e.x, dv * e.y);
        acc = gather_emb(x, off, dg, l, acc);
        float2 o;
        o.x = fmaxf(fmaf(dv, acc.x, bb.x), 0.f);
        o.y = fmaxf(fmaf(dv, acc.y, bb.y), 0.f);
        *(float2*)&As[(w << 3) + n][2 * l] = o;
    }
    __syncthreads();

    int tx = tid & 15, ty = tid >> 4;
    float acc[4][4] = {};
#pragma unroll
    for (int k = 0; k < 64; k++) {
        float4 bv = *(const float4*)&Ws[k * 64 + tx * 4];
#pragma unroll
        for (int r = 0; r < 4; r++) {
            float a = As[ty * 4 + r][k];
            acc[r][0] = fmaf(a, bv.x, acc[r][0]);
            acc[r][1] = fmaf(a, bv.y, acc[r][1]);
            acc[r][2] = fmaf(a, bv.z, acc[r][2]);
            acc[r][3] = fmaf(a, bv.w, acc[r][3]);
        }
    }
#pragma unroll
    for (int r = 0; r < 4; r++) {
        int v = base + ty * 4 + r;
        float dv = g_dinv[v];
        g_T2h[v * 32 + tx * 2]     = __floats2half2_rn(acc[r][0] * dv, acc[r][1] * dv);
        g_T2h[v * 32 + tx * 2 + 1] = __floats2half2_rn(acc[r][2] * dv, acc[r][3] * dv);
    }
}

// ---------------- layer2 gather + mean-pool fused ---------------------------
__global__ void k_gather_pool(const float* __restrict__ b2,
                              const int* __restrict__ batch) {
    __shared__ __align__(16) float As[64][68];
    __shared__ int sb[64];
    int tid = threadIdx.x;           // 256 threads
    int w = tid >> 5, l = tid & 31;
    int base = blockIdx.x * 64;
    if (tid < 64) sb[tid] = __ldg(&batch[base + tid]);
    float2 bb = __ldg(&((const float2*)b2)[l]);

    int offp = 0, degp = 0;
    if (l < 8) {
        int nv = base + (w << 3) + l;
        offp = g_off[nv];
        degp = g_deg[nv];
    }
#pragma unroll 1
    for (int n = 0; n < 8; n++) {
        int v = base + (w << 3) + n;
        int off = __shfl_sync(0xffffffffu, offp, n);
        int dg  = __shfl_sync(0xffffffffu, degp, n);
        float2 acc = __half22float2(__ldg(&g_T2h[v * 32 + l]));  // self loop
        acc = gather_T2(off, dg, l, acc);
        float dv = g_dinv[v];
        float2 o;
        o.x = fmaxf(fmaf(dv, acc.x, bb.x), 0.f);
        o.y = fmaxf(fmaf(dv, acc.y, bb.y), 0.f);
        *(float2*)&As[(w << 3) + n][2 * l] = o;
    }
    __syncthreads();

    // 64 threads: run-length pool over the 64 smem rows (batch is sorted)
    if (tid < 64) {
        int j = tid;
        int cur = sb[0];
        float acc = 0.f;
        int run = 0;
#pragma unroll 1
        for (int n = 0; n < 64; n++) {
            int gv = sb[n];
            if (gv != cur) {
                atomicAdd(&g_gsum[cur * 64 + j], acc);
                if (j == 0) atomicAdd(&g_cnt[cur], (float)run);
                acc = 0.f;
                run = 0;
                cur = gv;
            }
            acc += As[n][j];
            run++;
        }
        atomicAdd(&g_gsum[cur * 64 + j], acc);
        if (j == 0) atomicAdd(&g_cnt[cur], (float)run);
    }
}

// ---------------- classifier head ------------------------------------------
__global__ void k_final(const float* __restrict__ Wlin,
                        const float* __restrict__ blin,
                        float* __restrict__ out) {
    int g = blockIdx.x * blockDim.x + threadIdx.x;
    if (g >= NG) return;
    float inv = 1.0f / fmaxf(g_cnt[g], 1.0f);
    float a0 = blin[0], a1 = blin[1];
#pragma unroll 8
    for (int j = 0; j < 64; j++) {
        float m = g_gsum[g * 64 + j] * inv;
        a0 = fmaf(m, Wlin[2 * j], a0);
        a1 = fmaf(m, Wlin[2 * j + 1], a1);
    }
    out[2 * g] = a0;
    out[2 * g + 1] = a1;
}

// ---------------- launch ----------------------------------------------------
extern "C" void kernel_launch(void* const* d_in, const int* in_sizes, int n_in,
                              void* d_out, int out_size) {
    const int* x      = (const int*)d_in[0];
    const int* ei     = (const int*)d_in[1];   // [2, NE] row-major
    // d_in[2] = edge_type (unused by GCNConv)
    const int* batch  = (const int*)d_in[3];
    const float* emb  = (const float*)d_in[4];
    const float* W1   = (const float*)d_in[5];
    const float* b1   = (const float*)d_in[6];
    const float* W2   = (const float*)d_in[7];
    const float* b2   = (const float*)d_in[8];
    const float* Wlin = (const float*)d_in[9];
    const float* blin = (const float*)d_in[10];
    float* out = (float*)d_out;

    void* degp = nullptr;
    cudaGetSymbolAddress(&degp, g_deg);
    cudaMemsetAsync(degp, 0, NN * sizeof(int));

    k_count<<<(NE / 4 + 255) / 256, 256>>>(ei);
    k_scan<<<NBLK, 1024>>>();
    k_fill<<<(NE / 4 + 255) / 256, 256>>>(ei);

    k_embW<<<(NVOC + 63) / 64, 512>>>(emb, W1);

    k_gather_gemm<<<NN / 64, 256>>>(x, b1, W2);
    k_gather_pool<<<NN / 64, 256>>>(b2, batch);

    k_final<<<(NG + 255) / 256, 256>>>(Wlin, blin, out);
}

// round 5
// speedup vs baseline: 1.7215x; 1.0719x over previous
#include <cuda_runtime.h>
#include <cuda_fp16.h>

#define NN 200000
#define NE 1600000
#define NG 2000
#define DD 64
#define NVOC 10000
#define NBLK 196   // ceil(NN/1024)

// ---------------- scratch (static device globals; no allocations) ----------
__device__ int     g_deg[NN];
__device__ int     g_off[NN];
__device__ int     g_cur[NN];
__device__ float   g_dinv[NN];
__device__ int     g_csr[NE];
__device__ int     g_alloc;
__device__ __align__(16) __half2 g_embWh[NVOC * 32];  // fp16(emb@W1), 1.25MB
__device__ __align__(16) __half2 g_T2h[NN * 32];      // fp16(dinv*(h1@W2))
__device__ float   g_gsum[NG * DD];
__device__ float   g_cnt[NG];

__device__ __forceinline__ float4 h4_to_f4(uint2 u) {
    __half2 h0 = *reinterpret_cast<__half2*>(&u.x);
    __half2 h1 = *reinterpret_cast<__half2*>(&u.y);
    float2 a = __half22float2(h0), b = __half22float2(h1);
    return make_float4(a.x, a.y, b.x, b.y);
}

// ---------------- degree count (4 edges/thread) + zero pool bufs ------------
__global__ void k_count(const int* __restrict__ ei) {
    int t = blockIdx.x * blockDim.x + threadIdx.x;
    if (t == 0) g_alloc = 0;
    if (t < NG * DD) g_gsum[t] = 0.f;
    if (t < NG) g_cnt[t] = 0.f;
    int e = t * 4;
    if (e < NE) {
        int4 d4 = *(const int4*)&ei[NE + e];
        atomicAdd(&g_deg[d4.x], 1);
        atomicAdd(&g_deg[d4.y], 1);
        atomicAdd(&g_deg[d4.z], 1);
        atomicAdd(&g_deg[d4.w], 1);
    }
}

// ---------------- one-pass scan: disjoint CSR segments (order-free) --------
__global__ void k_scan() {
    int tid = threadIdx.x;
    int lane = tid & 31, wid = tid >> 5;
    int i = blockIdx.x * 1024 + tid;
    int v = (i < NN) ? g_deg[i] : 0;

    int xv = v;
#pragma unroll
    for (int d = 1; d < 32; d <<= 1) {
        int t = __shfl_up_sync(0xffffffffu, xv, d);
        if (lane >= d) xv += t;
    }
    __shared__ int wsum[32];
    if (lane == 31) wsum[wid] = xv;
    __syncthreads();
    if (tid < 32) {
        int y = wsum[tid];
#pragma unroll
        for (int d = 1; d < 32; d <<= 1) {
            int t = __shfl_up_sync(0xffffffffu, y, d);
            if (tid >= d) y += t;
        }
        wsum[tid] = y;
    }
    __syncthreads();
    int incl = xv + (wid > 0 ? wsum[wid - 1] : 0);

    __shared__ int sbase;
    if (tid == 1023) sbase = atomicAdd(&g_alloc, incl);  // incl == block total
    __syncthreads();

    if (i < NN) {
        int excl = sbase + incl - v;
        g_off[i] = excl;
        g_cur[i] = excl;
        g_dinv[i] = rsqrtf((float)(v + 1));
    }
}

__global__ void k_fill(const int* __restrict__ ei) {
    int e = (blockIdx.x * blockDim.x + threadIdx.x) * 4;
    if (e < NE) {
        int4 d4 = *(const int4*)&ei[NE + e];
        int4 s4 = *(const int4*)&ei[e];
        int p0 = atomicAdd(&g_cur[d4.x], 1);
        int p1 = atomicAdd(&g_cur[d4.y], 1);
        int p2 = atomicAdd(&g_cur[d4.z], 1);
        int p3 = atomicAdd(&g_cur[d4.w], 1);
        g_csr[p0] = s4.x;
        g_csr[p1] = s4.y;
        g_csr[p2] = s4.z;
        g_csr[p3] = s4.w;
    }
}

// ---------------- embWh = fp16(emb @ W1): 32-row tiles, 313 blocks ----------
__global__ void k_embW(const float* __restrict__ emb,
                       const float* __restrict__ W) {
    __shared__ __align__(16) float Ws[64 * 64];
    __shared__ __align__(16) float As[32][68];
    int tid = threadIdx.x;           // 256 threads
    for (int i = tid; i < 4096; i += 256) Ws[i] = W[i];
    int rowbase = blockIdx.x * 32;
#pragma unroll
    for (int q = 0; q < 2; q++) {
        int lin4 = q * 256 + tid;            // 512 float4 = 32x64 floats
        int r = lin4 >> 4;
        int cc = (lin4 & 15) << 2;
        int v = rowbase + r;
        float4 val = make_float4(0.f, 0.f, 0.f, 0.f);
        if (v < NVOC) val = *(const float4*)&emb[v * 64 + cc];
        *(float4*)&As[r][cc] = val;
    }
    __syncthreads();

    int tx = tid & 15, ty = tid >> 4;        // ty: 0..15, 2 rows each
    float acc[2][4] = {};
#pragma unroll
    for (int k = 0; k < 64; k++) {
        float4 bv = *(const float4*)&Ws[k * 64 + tx * 4];
#pragma unroll
        for (int r = 0; r < 2; r++) {
            float a = As[ty * 2 + r][k];
            acc[r][0] = fmaf(a, bv.x, acc[r][0]);
            acc[r][1] = fmaf(a, bv.y, acc[r][1]);
            acc[r][2] = fmaf(a, bv.z, acc[r][2]);
            acc[r][3] = fmaf(a, bv.w, acc[r][3]);
        }
    }
#pragma unroll
    for (int r = 0; r < 2; r++) {
        int v = rowbase + ty * 2 + r;
        if (v < NVOC) {
            g_embWh[v * 32 + tx * 2]     = __floats2half2_rn(acc[r][0], acc[r][1]);
            g_embWh[v * 32 + tx * 2 + 1] = __floats2half2_rn(acc[r][2], acc[r][3]);
        }
    }
}

// ---------------- layer1 gather (2 nodes/warp, uint2 lanes) + layer2 GEMM ---
__global__ void k_gather_gemm(const int* __restrict__ x,
                              const float* __restrict__ b1,
                              const float* __restrict__ W2) {
    __shared__ __align__(16) float Ws[64 * 64];
    __shared__ __align__(16) float As[64][68];
    int tid = threadIdx.x;           // 256 threads
    int w = tid >> 5, l = tid & 31;
    int half = l >> 4, li = l & 15;
    for (int i = tid; i < 4096; i += 256) Ws[i] = W2[i];
    int base = blockIdx.x * 64;
    float4 bb = __ldg(&((const float4*)b1)[li]);
    const uint2* ew = (const uint2*)g_embWh;

    int offp = 0, degp = 0, tokp = 0;
    float dvp = 0.f;
    if (l < 8) {
        int nv = base + (w << 3) + l;
        offp = g_off[nv];
        degp = g_deg[nv];
        tokp = __ldg(&x[nv]);
        dvp  = g_dinv[nv];
    }
#pragma unroll 1
    for (int it = 0; it < 4; it++) {
        int na  = 2 * it + half;
        int off = __shfl_sync(0xffffffffu, offp, na);
        int dg  = __shfl_sync(0xffffffffu, degp, na);
        int tok = __shfl_sync(0xffffffffu, tokp, na);
        float dv = __shfl_sync(0xffffffffu, dvp, na);
        int dgo = __shfl_sync(0xffffffffu, degp, 2 * it + (half ^ 1));
        int dgmax = max(dg, dgo);

        float4 e = h4_to_f4(__ldg(&ew[tok * 16 + li]));   // self loop
        float4 acc = make_float4(dv * e.x, dv * e.y, dv * e.z, dv * e.w);
        const int* cs = g_csr + off;
#pragma unroll 1
        for (int i = 0; i < dgmax; i += 4) {
#pragma unroll
            for (int j = 0; j < 4; j++) {
                int eidx = i + j;
                if (eidx < dg) {
                    int s  = __ldg(&cs[eidx]);
                    int xs = __ldg(&x[s]);
                    float ds = __ldg(&g_dinv[s]);
                    float4 v = h4_to_f4(__ldg(&ew[xs * 16 + li]));
                    acc.x = fmaf(ds, v.x, acc.x);
                    acc.y = fmaf(ds, v.y, acc.y);
                    acc.z = fmaf(ds, v.z, acc.z);
                    acc.w = fmaf(ds, v.w, acc.w);
                }
            }
        }
        float4 o;
        o.x = fmaxf(fmaf(dv, acc.x, bb.x), 0.f);
        o.y = fmaxf(fmaf(dv, acc.y, bb.y), 0.f);
        o.z = fmaxf(fmaf(dv, acc.z, bb.z), 0.f);
        o.w = fmaxf(fmaf(dv, acc.w, bb.w), 0.f);
        *(float4*)&As[(w << 3) + na][li * 4] = o;
    }
    __syncthreads();

    int tx = tid & 15, ty = tid >> 4;
    float acc[4][4] = {};
#pragma unroll
    for (int k = 0; k < 64; k++) {
        float4 bv = *(const float4*)&Ws[k * 64 + tx * 4];
#pragma unroll
        for (int r = 0; r < 4; r++) {
            float a = As[ty * 4 + r][k];
            acc[r][0] = fmaf(a, bv.x, acc[r][0]);
            acc[r][1] = fmaf(a, bv.y, acc[r][1]);
            acc[r][2] = fmaf(a, bv.z, acc[r][2]);
            acc[r][3] = fmaf(a, bv.w, acc[r][3]);
        }
    }
#pragma unroll
    for (int r = 0; r < 4; r++) {
        int v = base + ty * 4 + r;
        float dv = g_dinv[v];
        g_T2h[v * 32 + tx * 2]     = __floats2half2_rn(acc[r][0] * dv, acc[r][1] * dv);
        g_T2h[v * 32 + tx * 2 + 1] = __floats2half2_rn(acc[r][2] * dv, acc[r][3] * dv);
    }
}

// ---------------- layer2 gather (2 nodes/warp) + mean-pool fused ------------
__global__ void k_gather_pool(const float* __restrict__ b2,
                              const int* __restrict__ batch) {
    __shared__ __align__(16) float As[64][68];
    __shared__ int sb[64];
    int tid = threadIdx.x;           // 256 threads
    int w = tid >> 5, l = tid & 31;
    int half = l >> 4, li = l & 15;
    int base = blockIdx.x * 64;
    if (tid < 64) sb[tid] = __ldg(&batch[base + tid]);
    float4 bb = __ldg(&((const float4*)b2)[li]);
    const uint2* tv = (const uint2*)g_T2h;

    int offp = 0, degp = 0;
    float dvp = 0.f;
    if (l < 8) {
        int nv = base + (w << 3) + l;
        offp = g_off[nv];
        degp = g_deg[nv];
        dvp  = g_dinv[nv];
    }
#pragma unroll 1
    for (int it = 0; it < 4; it++) {
        int na  = 2 * it + half;
        int v   = base + (w << 3) + na;
        int off = __shfl_sync(0xffffffffu, offp, na);
        int dg  = __shfl_sync(0xffffffffu, degp, na);
        float dv = __shfl_sync(0xffffffffu, dvp, na);
        int dgo = __shfl_sync(0xffffffffu, degp, 2 * it + (half ^ 1));
        int dgmax = max(dg, dgo);

        float4 acc = h4_to_f4(__ldg(&tv[v * 16 + li]));   // self loop
        const int* cs = g_csr + off;
#pragma unroll 1
        for (int i = 0; i < dgmax; i += 4) {
#pragma unroll
            for (int j = 0; j < 4; j++) {
                int eidx = i + j;
                if (eidx < dg) {
                    int s = __ldg(&cs[eidx]);
                    float4 vv = h4_to_f4(__ldg(&tv[s * 16 + li]));
                    acc.x += vv.x;
                    acc.y += vv.y;
                    acc.z += vv.z;
                    acc.w += vv.w;
                }
            }
        }
        float4 o;
        o.x = fmaxf(fmaf(dv, acc.x, bb.x), 0.f);
        o.y = fmaxf(fmaf(dv, acc.y, bb.y), 0.f);
        o.z = fmaxf(fmaf(dv, acc.z, bb.z), 0.f);
        o.w = fmaxf(fmaf(dv, acc.w, bb.w), 0.f);
        *(float4*)&As[(w << 3) + na][li * 4] = o;
    }
    __syncthreads();

    // 64 threads: run-length pool over the 64 smem rows (batch is sorted)
    if (tid < 64) {
        int j = tid;
        int cur = sb[0];
        float acc = 0.f;
        int run = 0;
#pragma unroll 1
        for (int n = 0; n < 64; n++) {
            int gv = sb[n];
            if (gv != cur) {
                atomicAdd(&g_gsum[cur * 64 + j], acc);
                if (j == 0) atomicAdd(&g_cnt[cur], (float)run);
                acc = 0.f;
                run = 0;
                cur = gv;
            }
            acc += As[n][j];
            run++;
        }
        atomicAdd(&g_gsum[cur * 64 + j], acc);
        if (j == 0) atomicAdd(&g_cnt[cur], (float)run);
    }
}

// ---------------- classifier head ------------------------------------------
__global__ void k_final(const float* __restrict__ Wlin,
                        const float* __restrict__ blin,
                        float* __restrict__ out) {
    int g = blockIdx.x * blockDim.x + threadIdx.x;
    if (g >= NG) return;
    float inv = 1.0f / fmaxf(g_cnt[g], 1.0f);
    float a0 = blin[0], a1 = blin[1];
#pragma unroll 8
    for (int j = 0; j < 64; j++) {
        float m = g_gsum[g * 64 + j] * inv;
        a0 = fmaf(m, Wlin[2 * j], a0);
        a1 = fmaf(m, Wlin[2 * j + 1], a1);
    }
    out[2 * g] = a0;
    out[2 * g + 1] = a1;
}

// ---------------- launch ----------------------------------------------------
extern "C" void kernel_launch(void* const* d_in, const int* in_sizes, int n_in,
                              void* d_out, int out_size) {
    const int* x      = (const int*)d_in[0];
    const int* ei     = (const int*)d_in[1];   // [2, NE] row-major
    // d_in[2] = edge_type (unused by GCNConv)
    const int* batch  = (const int*)d_in[3];
    const float* emb  = (const float*)d_in[4];
    const float* W1   = (const float*)d_in[5];
    const float* b1   = (const float*)d_in[6];
    const float* W2   = (const float*)d_in[7];
    const float* b2   = (const float*)d_in[8];
    const float* Wlin = (const float*)d_in[9];
    const float* blin = (const float*)d_in[10];
    float* out = (float*)d_out;

    void* degp = nullptr;
    cudaGetSymbolAddress(&degp, g_deg);
    cudaMemsetAsync(degp, 0, NN * sizeof(int));

    k_count<<<(NE / 4 + 255) / 256, 256>>>(ei);
    k_scan<<<NBLK, 1024>>>();
    k_fill<<<(NE / 4 + 255) / 256, 256>>>(ei);

    k_embW<<<(NVOC + 31) / 32, 256>>>(emb, W1);

    k_gather_gemm<<<NN / 64, 256>>>(x, b1, W2);
    k_gather_pool<<<NN / 64, 256>>>(b2, batch);

    k_final<<<(NG + 255) / 256, 256>>>(Wlin, blin, out);
}

// round 6
// speedup vs baseline: 1.7975x; 1.0441x over previous
#include <cuda_runtime.h>
#include <cuda_fp16.h>

#define NN 200000
#define NE 1600000
#define NG 2000
#define DD 64
#define NVOC 10000
#define NBLK 196        // ceil(NN/1024)
#define EMBB 313        // embW blocks (32 rows each)
#define CNTB 1563       // count blocks (1024 edges each, 4/thread)

// ---------------- scratch (static device globals; no allocations) ----------
__device__ int     g_deg[NN];
__device__ int     g_off[NN];
__device__ int     g_cur[NN];
__device__ float   g_dinv[NN];
__device__ int     g_csr[NE];
__device__ int     g_alloc;
__device__ __align__(16) __half2 g_embWh[NVOC * 32];  // fp16(emb@W1), 1.25MB
__device__ __align__(16) __half2 g_T2h[NN * 32];      // fp16(dinv*(h1@W2))
__device__ float   g_gsum[NG * DD];
__device__ float   g_cnt[NG];

// ---------------- fused: embW GEMM (blocks <EMBB) + degree count ------------
__global__ void k_prep(const float* __restrict__ emb,
                       const float* __restrict__ W,
                       const int* __restrict__ ei) {
    __shared__ __align__(16) float Ws[64 * 64];
    __shared__ __align__(16) float As[32][68];
    int tid = threadIdx.x;           // 256 threads
    if (blockIdx.x >= EMBB) {
        // ---- degree count path ----
        int t = (blockIdx.x - EMBB) * 256 + tid;
        if (t == 0) g_alloc = 0;
        if (t < NG * DD) g_gsum[t] = 0.f;
        if (t < NG) g_cnt[t] = 0.f;
        int e = t * 4;
        if (e < NE) {
            int4 d4 = *(const int4*)&ei[NE + e];
            atomicAdd(&g_deg[d4.x], 1);
            atomicAdd(&g_deg[d4.y], 1);
            atomicAdd(&g_deg[d4.z], 1);
            atomicAdd(&g_deg[d4.w], 1);
        }
        return;
    }
    // ---- embW path ----
    for (int i = tid; i < 4096; i += 256) Ws[i] = W[i];
    int rowbase = blockIdx.x * 32;
#pragma unroll
    for (int q = 0; q < 2; q++) {
        int lin4 = q * 256 + tid;
        int r = lin4 >> 4;
        int cc = (lin4 & 15) << 2;
        int v = rowbase + r;
        float4 val = make_float4(0.f, 0.f, 0.f, 0.f);
        if (v < NVOC) val = *(const float4*)&emb[v * 64 + cc];
        *(float4*)&As[r][cc] = val;
    }
    __syncthreads();

    int tx = tid & 15, ty = tid >> 4;
    float acc[2][4] = {};
#pragma unroll
    for (int k = 0; k < 64; k++) {
        float4 bv = *(const float4*)&Ws[k * 64 + tx * 4];
#pragma unroll
        for (int r = 0; r < 2; r++) {
            float a = As[ty * 2 + r][k];
            acc[r][0] = fmaf(a, bv.x, acc[r][0]);
            acc[r][1] = fmaf(a, bv.y, acc[r][1]);
            acc[r][2] = fmaf(a, bv.z, acc[r][2]);
            acc[r][3] = fmaf(a, bv.w, acc[r][3]);
        }
    }
#pragma unroll
    for (int r = 0; r < 2; r++) {
        int v = rowbase + ty * 2 + r;
        if (v < NVOC) {
            g_embWh[v * 32 + tx * 2]     = __floats2half2_rn(acc[r][0], acc[r][1]);
            g_embWh[v * 32 + tx * 2 + 1] = __floats2half2_rn(acc[r][2], acc[r][3]);
        }
    }
}

// ---------------- one-pass scan: disjoint CSR segments (order-free) --------
__global__ void k_scan() {
    int tid = threadIdx.x;
    int lane = tid & 31, wid = tid >> 5;
    int i = blockIdx.x * 1024 + tid;
    int v = (i < NN) ? g_deg[i] : 0;

    int xv = v;
#pragma unroll
    for (int d = 1; d < 32; d <<= 1) {
        int t = __shfl_up_sync(0xffffffffu, xv, d);
        if (lane >= d) xv += t;
    }
    __shared__ int wsum[32];
    if (lane == 31) wsum[wid] = xv;
    __syncthreads();
    if (tid < 32) {
        int y = wsum[tid];
#pragma unroll
        for (int d = 1; d < 32; d <<= 1) {
            int t = __shfl_up_sync(0xffffffffu, y, d);
            if (tid >= d) y += t;
        }
        wsum[tid] = y;
    }
    __syncthreads();
    int incl = xv + (wid > 0 ? wsum[wid - 1] : 0);

    __shared__ int sbase;
    if (tid == 1023) sbase = atomicAdd(&g_alloc, incl);
    __syncthreads();

    if (i < NN) {
        int excl = sbase + incl - v;
        g_off[i] = excl;
        g_cur[i] = excl;
        g_dinv[i] = rsqrtf((float)(v + 1));
    }
}

__global__ void k_fill(const int* __restrict__ ei) {
    int e = (blockIdx.x * blockDim.x + threadIdx.x) * 4;
    if (e < NE) {
        int4 d4 = *(const int4*)&ei[NE + e];
        int4 s4 = *(const int4*)&ei[e];
        int p0 = atomicAdd(&g_cur[d4.x], 1);
        int p1 = atomicAdd(&g_cur[d4.y], 1);
        int p2 = atomicAdd(&g_cur[d4.z], 1);
        int p3 = atomicAdd(&g_cur[d4.w], 1);
        g_csr[p0] = s4.x;
        g_csr[p1] = s4.y;
        g_csr[p2] = s4.z;
        g_csr[p3] = s4.w;
    }
}

// ---------------- half8 (uint4) -> 8 floats ---------------------------------
struct f8 { float v[8]; };
__device__ __forceinline__ f8 h8_to_f8(uint4 u) {
    f8 r;
    float2 a = __half22float2(*reinterpret_cast<__half2*>(&u.x));
    float2 b = __half22float2(*reinterpret_cast<__half2*>(&u.y));
    float2 c = __half22float2(*reinterpret_cast<__half2*>(&u.z));
    float2 d = __half22float2(*reinterpret_cast<__half2*>(&u.w));
    r.v[0] = a.x; r.v[1] = a.y; r.v[2] = b.x; r.v[3] = b.y;
    r.v[4] = c.x; r.v[5] = c.y; r.v[6] = d.x; r.v[7] = d.y;
    return r;
}

// ---------------- layer1 gather (4 nodes/warp, uint4 lanes) + layer2 GEMM ---
__global__ void k_gather_gemm(const int* __restrict__ x,
                              const float* __restrict__ b1,
                              const float* __restrict__ W2) {
    __shared__ __align__(16) float Ws[64 * 64];
    __shared__ __align__(16) float As[64][68];
    int tid = threadIdx.x;           // 256 threads
    int w = tid >> 5, l = tid & 31;
    int q = l >> 3, li = l & 7;
    for (int i = tid; i < 4096; i += 256) Ws[i] = W2[i];
    int base = blockIdx.x * 64;
    float4 bb0 = __ldg(&((const float4*)b1)[li * 2]);
    float4 bb1 = __ldg(&((const float4*)b1)[li * 2 + 1]);
    const uint4* ew = (const uint4*)g_embWh;

    int offp = 0, degp = 0, tokp = 0;
    float dvp = 0.f;
    if (l < 8) {
        int nv = base + (w << 3) + l;
        offp = g_off[nv];
        degp = g_deg[nv];
        tokp = __ldg(&x[nv]);
        dvp  = g_dinv[nv];
    }
#pragma unroll
    for (int it = 0; it < 2; it++) {
        int na  = it * 4 + q;
        int off = __shfl_sync(0xffffffffu, offp, na);
        int dg  = __shfl_sync(0xffffffffu, degp, na);
        int tok = __shfl_sync(0xffffffffu, tokp, na);
        float dv = __shfl_sync(0xffffffffu, dvp, na);
        int d0 = __shfl_sync(0xffffffffu, degp, it * 4);
        int d1 = __shfl_sync(0xffffffffu, degp, it * 4 + 1);
        int d2 = __shfl_sync(0xffffffffu, degp, it * 4 + 2);
        int d3 = __shfl_sync(0xffffffffu, degp, it * 4 + 3);
        int dgmax = max(max(d0, d1), max(d2, d3));

        f8 e = h8_to_f8(__ldg(&ew[tok * 8 + li]));   // self loop
        float acc[8];
#pragma unroll
        for (int k = 0; k < 8; k++) acc[k] = dv * e.v[k];

        const int* cs = g_csr + off;
#pragma unroll 1
        for (int i = 0; i < dgmax; i += 4) {
            int   s[4];
            int   xs[4];
            float ds[4];
#pragma unroll
            for (int j = 0; j < 4; j++)
                s[j] = (i + j < dg) ? __ldg(&cs[i + j]) : -1;
#pragma unroll
            for (int j = 0; j < 4; j++) {
                xs[j] = (s[j] >= 0) ? __ldg(&x[s[j]]) : 0;
                ds[j] = (s[j] >= 0) ? __ldg(&g_dinv[s[j]]) : 0.f;
            }
#pragma unroll
            for (int j = 0; j < 4; j++) {
                if (s[j] >= 0) {
                    f8 r = h8_to_f8(__ldg(&ew[xs[j] * 8 + li]));
#pragma unroll
                    for (int k = 0; k < 8; k++)
                        acc[k] = fmaf(ds[j], r.v[k], acc[k]);
                }
            }
        }
        float o[8];
        o[0] = fmaxf(fmaf(dv, acc[0], bb0.x), 0.f);
        o[1] = fmaxf(fmaf(dv, acc[1], bb0.y), 0.f);
        o[2] = fmaxf(fmaf(dv, acc[2], bb0.z), 0.f);
        o[3] = fmaxf(fmaf(dv, acc[3], bb0.w), 0.f);
        o[4] = fmaxf(fmaf(dv, acc[4], bb1.x), 0.f);
        o[5] = fmaxf(fmaf(dv, acc[5], bb1.y), 0.f);
        o[6] = fmaxf(fmaf(dv, acc[6], bb1.z), 0.f);
        o[7] = fmaxf(fmaf(dv, acc[7], bb1.w), 0.f);
        int row = (w << 3) + na;
        *(float4*)&As[row][li * 8]     = make_float4(o[0], o[1], o[2], o[3]);
        *(float4*)&As[row][li * 8 + 4] = make_float4(o[4], o[5], o[6], o[7]);
    }
    __syncthreads();

    int tx = tid & 15, ty = tid >> 4;
    float acc[4][4] = {};
#pragma unroll
    for (int k = 0; k < 64; k++) {
        float4 bv = *(const float4*)&Ws[k * 64 + tx * 4];
#pragma unroll
        for (int r = 0; r < 4; r++) {
            float a = As[ty * 4 + r][k];
            acc[r][0] = fmaf(a, bv.x, acc[r][0]);
            acc[r][1] = fmaf(a, bv.y, acc[r][1]);
            acc[r][2] = fmaf(a, bv.z, acc[r][2]);
            acc[r][3] = fmaf(a, bv.w, acc[r][3]);
        }
    }
#pragma unroll
    for (int r = 0; r < 4; r++) {
        int v = base + ty * 4 + r;
        float dv = g_dinv[v];
        g_T2h[v * 32 + tx * 2]     = __floats2half2_rn(acc[r][0] * dv, acc[r][1] * dv);
        g_T2h[v * 32 + tx * 2 + 1] = __floats2half2_rn(acc[r][2] * dv, acc[r][3] * dv);
    }
}

// ---------------- layer2 gather (4 nodes/warp) + mean-pool fused ------------
__global__ void k_gather_pool(const float* __restrict__ b2,
                              const int* __restrict__ batch) {
    __shared__ __align__(16) float As[64][68];
    __shared__ int sb[64];
    int tid = threadIdx.x;           // 256 threads
    int w = tid >> 5, l = tid & 31;
    int q = l >> 3, li = l & 7;
    int base = blockIdx.x * 64;
    if (tid < 64) sb[tid] = __ldg(&batch[base + tid]);
    float4 bb0 = __ldg(&((const float4*)b2)[li * 2]);
    float4 bb1 = __ldg(&((const float4*)b2)[li * 2 + 1]);
    const uint4* tv = (const uint4*)g_T2h;

    int offp = 0, degp = 0;
    float dvp = 0.f;
    if (l < 8) {
        int nv = base + (w << 3) + l;
        offp = g_off[nv];
        degp = g_deg[nv];
        dvp  = g_dinv[nv];
    }
#pragma unroll
    for (int it = 0; it < 2; it++) {
        int na  = it * 4 + q;
        int v   = base + (w << 3) + na;
        int off = __shfl_sync(0xffffffffu, offp, na);
        int dg  = __shfl_sync(0xffffffffu, degp, na);
        float dv = __shfl_sync(0xffffffffu, dvp, na);
        int d0 = __shfl_sync(0xffffffffu, degp, it * 4);
        int d1 = __shfl_sync(0xffffffffu, degp, it * 4 + 1);
        int d2 = __shfl_sync(0xffffffffu, degp, it * 4 + 2);
        int d3 = __shfl_sync(0xffffffffu, degp, it * 4 + 3);
        int dgmax = max(max(d0, d1), max(d2, d3));

        f8 e = h8_to_f8(__ldg(&tv[v * 8 + li]));     // self loop
        float acc[8];
#pragma unroll
        for (int k = 0; k < 8; k++) acc[k] = e.v[k];

        const int* cs = g_csr + off;
#pragma unroll 1
        for (int i = 0; i < dgmax; i += 4) {
            int s[4];
#pragma unroll
            for (int j = 0; j < 4; j++)
                s[j] = (i + j < dg) ? __ldg(&cs[i + j]) : -1;
#pragma unroll
            for (int j = 0; j < 4; j++) {
                if (s[j] >= 0) {
                    f8 r = h8_to_f8(__ldg(&tv[s[j] * 8 + li]));
#pragma unroll
                    for (int k = 0; k < 8; k++) acc[k] += r.v[k];
                }
            }
        }
        float o[8];
        o[0] = fmaxf(fmaf(dv, acc[0], bb0.x), 0.f);
        o[1] = fmaxf(fmaf(dv, acc[1], bb0.y), 0.f);
        o[2] = fmaxf(fmaf(dv, acc[2], bb0.z), 0.f);
        o[3] = fmaxf(fmaf(dv, acc[3], bb0.w), 0.f);
        o[4] = fmaxf(fmaf(dv, acc[4], bb1.x), 0.f);
        o[5] = fmaxf(fmaf(dv, acc[5], bb1.y), 0.f);
        o[6] = fmaxf(fmaf(dv, acc[6], bb1.z), 0.f);
        o[7] = fmaxf(fmaf(dv, acc[7], bb1.w), 0.f);
        int row = (w << 3) + na;
        *(float4*)&As[row][li * 8]     = make_float4(o[0], o[1], o[2], o[3]);
        *(float4*)&As[row][li * 8 + 4] = make_float4(o[4], o[5], o[6], o[7]);
    }
    __syncthreads();

    // 64 threads: run-length pool over the 64 smem rows (batch is sorted)
    if (tid < 64) {
        int j = tid;
        int cur = sb[0];
        float acc = 0.f;
        int run = 0;
#pragma unroll 1
        for (int n = 0; n < 64; n++) {
            int gv = sb[n];
            if (gv != cur) {
                atomicAdd(&g_gsum[cur * 64 + j], acc);
                if (j == 0) atomicAdd(&g_cnt[cur], (float)run);
                acc = 0.f;
                run = 0;
                cur = gv;
            }
            acc += As[n][j];
            run++;
        }
        atomicAdd(&g_gsum[cur * 64 + j], acc);
        if (j == 0) atomicAdd(&g_cnt[cur], (float)run);
    }
}

// ---------------- classifier head ------------------------------------------
__global__ void k_final(const float* __restrict__ Wlin,
                        const float* __restrict__ blin,
                        float* __restrict__ out) {
    int g = blockIdx.x * blockDim.x + threadIdx.x;
    if (g >= NG) return;
    float inv = 1.0f / fmaxf(g_cnt[g], 1.0f);
    float a0 = blin[0], a1 = blin[1];
#pragma unroll 8
    for (int j = 0; j < 64; j++) {
        float m = g_gsum[g * 64 + j] * inv;
        a0 = fmaf(m, Wlin[2 * j], a0);
        a1 = fmaf(m, Wlin[2 * j + 1], a1);
    }
    out[2 * g] = a0;
    out[2 * g + 1] = a1;
}

// ---------------- launch ----------------------------------------------------
extern "C" void kernel_launch(void* const* d_in, const int* in_sizes, int n_in,
                              void* d_out, int out_size) {
    const int* x      = (const int*)d_in[0];
    const int* ei     = (const int*)d_in[1];   // [2, NE] row-major
    // d_in[2] = edge_type (unused by GCNConv)
    const int* batch  = (const int*)d_in[3];
    const float* emb  = (const float*)d_in[4];
    const float* W1   = (const float*)d_in[5];
    const float* b1   = (const float*)d_in[6];
    const float* W2   = (const float*)d_in[7];
    const float* b2   = (const float*)d_in[8];
    const float* Wlin = (const float*)d_in[9];
    const float* blin = (const float*)d_in[10];
    float* out = (float*)d_out;

    void* degp = nullptr;
    cudaGetSymbolAddress(&degp, g_deg);
    cudaMemsetAsync(degp, 0, NN * sizeof(int));

    k_prep<<<EMBB + CNTB, 256>>>(emb, W1, ei);   // embW GEMM + degree count
    k_scan<<<NBLK, 1024>>>();
    k_fill<<<(NE / 4 + 255) / 256, 256>>>(ei);

    k_gather_gemm<<<NN / 64, 256>>>(x, b1, W2);
    k_gather_pool<<<NN / 64, 256>>>(b2, batch);

    k_final<<<(NG + 255) / 256, 256>>>(Wlin, blin, out);
}